// round 8
// baseline (speedup 1.0000x reference)
#include <cuda_runtime.h>

#define N_NODES 50000
#define N_EDGES 800000
#define F_IN    128
#define H_DIM   100
#define C_DIM   16
#define LEAKY   0.01f

#define SCAN_BLK 49              // ceil(50000/1024)

// ---- scratch (device globals; no allocation allowed) ----
__device__ __align__(16) float g_h1 [N_NODES * H_DIM];   // X @ W1
__device__ __align__(16) float g_h1p[N_NODES * H_DIM];   // leaky(conv1 out)
__device__ __align__(16) float g_h2 [N_NODES * C_DIM];   // h1p @ W2
__device__ float g_dinv[N_NODES];
__device__ __align__(16) int g_cnt[N_NODES];             // ZERO at entry (static init + scanF re-zero)
__device__ __align__(16) int g_rank[N_EDGES];            // edge rank within dst bucket
__device__ int   g_rowptr[N_NODES + 1];
__device__ int   g_col[N_EDGES];
__device__ float g_val[N_EDGES];                         // written by prop1f, read by prop2f
__device__ int   g_bsum[SCAN_BLK];
__device__ int            g_bar_cnt = 0;
__device__ volatile int   g_bar_gen = 0;

// ---------------------------------------------------------------- count + rank, 8 edges/thread
__global__ void k_count(const int* __restrict__ dst) {
    int t = blockIdx.x * blockDim.x + threadIdx.x;
    if (t >= N_EDGES / 8) return;
    int4 d0 = ((const int4*)dst)[t * 2];
    int4 d1 = ((const int4*)dst)[t * 2 + 1];
    int4 r0, r1;
    r0.x = atomicAdd(&g_cnt[d0.x], 1);
    r0.y = atomicAdd(&g_cnt[d0.y], 1);
    r0.z = atomicAdd(&g_cnt[d0.z], 1);
    r0.w = atomicAdd(&g_cnt[d0.w], 1);
    r1.x = atomicAdd(&g_cnt[d1.x], 1);
    r1.y = atomicAdd(&g_cnt[d1.y], 1);
    r1.z = atomicAdd(&g_cnt[d1.z], 1);
    r1.w = atomicAdd(&g_cnt[d1.w], 1);
    ((int4*)g_rank)[t * 2]     = r0;
    ((int4*)g_rank)[t * 2 + 1] = r1;
}

// ---------------------------------------------------------------- fused scan (49 blocks, internal grid barrier)
// Also re-zeroes g_cnt to restore the entry invariant for the next replay.
__global__ void k_scanF() {
    __shared__ int wsum[32];
    __shared__ int s_pref[64];
    __shared__ int s_w0tot;
    int b = blockIdx.x, tid = threadIdx.x, lane = tid & 31, wid = tid >> 5;
    int i = b * 1024 + tid;
    int v = 0;
    if (i < N_NODES) {
        v = g_cnt[i];
        g_cnt[i] = 0;                       // restore invariant
    }

    int incl = v;
    #pragma unroll
    for (int off = 1; off < 32; off <<= 1) {
        int t = __shfl_up_sync(0xFFFFFFFFu, incl, off);
        if (lane >= off) incl += t;
    }
    if (lane == 31) wsum[wid] = incl;
    __syncthreads();
    if (wid == 0) {
        int wv = wsum[lane];
        int winc = wv;
        #pragma unroll
        for (int off = 1; off < 32; off <<= 1) {
            int t = __shfl_up_sync(0xFFFFFFFFu, winc, off);
            if (lane >= off) winc += t;
        }
        wsum[lane] = winc - wv;
        if (lane == 31) g_bsum[b] = winc;   // block total
    }
    __syncthreads();
    int excl_in_blk = wsum[wid] + incl - v;

    // 49-block grid barrier (co-resident: 49 < 148 SMs)
    __syncthreads();
    if (tid == 0) {
        __threadfence();
        int gen = g_bar_gen;
        if (atomicAdd(&g_bar_cnt, 1) == SCAN_BLK - 1) {
            g_bar_cnt = 0;
            __threadfence();
            g_bar_gen = gen + 1;
        } else {
            while (g_bar_gen == gen) __nanosleep(32);
            __threadfence();
        }
    }
    __syncthreads();

    // parallel exclusive scan of the 49 block totals (2 warps).
    if (tid < 64) {
        int bv = (tid < SCAN_BLK) ? g_bsum[tid] : 0;
        int binc = bv;
        #pragma unroll
        for (int off = 1; off < 32; off <<= 1) {
            int t = __shfl_up_sync(0xFFFFFFFFu, binc, off);
            if (lane >= off) binc += t;
        }
        s_pref[tid] = binc - bv;             // exclusive within warp
        if (tid == 31) s_w0tot = binc;       // warp-0 inclusive total (own slot; R6 race fix)
    }
    __syncthreads();
    if (tid >= 32 && tid < 64) s_pref[tid] += s_w0tot;
    __syncthreads();

    int e = s_pref[b] + excl_in_blk;
    if (i < N_NODES) {
        g_rowptr[i] = e;
        g_dinv[i]   = rsqrtf((float)(v + 1));
    }
    if (b == 0 && tid == 0) g_rowptr[N_NODES] = N_EDGES;
}

// ---------------------------------------------------------------- build CSR: col only (val computed in prop1f), 8 edges/thread
__global__ void k_build(const int* __restrict__ src, const int* __restrict__ dst) {
    int t = blockIdx.x * blockDim.x + threadIdx.x;
    if (t >= N_EDGES / 8) return;
    int4 s0 = ((const int4*)src)[t * 2];
    int4 s1 = ((const int4*)src)[t * 2 + 1];
    int4 d0 = ((const int4*)dst)[t * 2];
    int4 d1 = ((const int4*)dst)[t * 2 + 1];
    int4 r0 = ((const int4*)g_rank)[t * 2];
    int4 r1 = ((const int4*)g_rank)[t * 2 + 1];
    int sv[8] = {s0.x, s0.y, s0.z, s0.w, s1.x, s1.y, s1.z, s1.w};
    int dv[8] = {d0.x, d0.y, d0.z, d0.w, d1.x, d1.y, d1.z, d1.w};
    int rv[8] = {r0.x, r0.y, r0.z, r0.w, r1.x, r1.y, r1.z, r1.w};
    #pragma unroll
    for (int k = 0; k < 8; k++)
        g_col[g_rowptr[dv[k]] + rv[k]] = sv[k];
}

// ---------------------------------------------------------------- GEMM1: g_h1 = x @ W1   (N x 128 @ 128 x 100)
__global__ void k_gemm1(const float* __restrict__ x, const float* __restrict__ W1) {
    __shared__ __align__(16) float sxT[8][128];
    __shared__ __align__(16) float sw [8][128];

    int tid  = threadIdx.x;
    int tcol = tid & 15;
    int trow = tid >> 4;
    int r0   = blockIdx.x * 128;

    float acc[8][8];
    #pragma unroll
    for (int i = 0; i < 8; i++)
        #pragma unroll
        for (int j = 0; j < 8; j++) acc[i][j] = 0.f;

    int xrow  = tid >> 1;
    int xhalf = tid & 1;
    int wrow  = tid >> 5;
    int wcol  = (tid & 31) * 4;

    for (int k0 = 0; k0 < F_IN; k0 += 8) {
        float4 xv = make_float4(0.f, 0.f, 0.f, 0.f);
        int gr = r0 + xrow;
        if (gr < N_NODES) xv = *(const float4*)&x[gr * F_IN + k0 + xhalf * 4];
        sxT[xhalf * 4 + 0][xrow] = xv.x;
        sxT[xhalf * 4 + 1][xrow] = xv.y;
        sxT[xhalf * 4 + 2][xrow] = xv.z;
        sxT[xhalf * 4 + 3][xrow] = xv.w;
        float4 wv = make_float4(0.f, 0.f, 0.f, 0.f);
        if (wcol < H_DIM) wv = *(const float4*)&W1[(k0 + wrow) * H_DIM + wcol];
        *(float4*)&sw[wrow][wcol] = wv;
        __syncthreads();

        #pragma unroll
        for (int k = 0; k < 8; k++) {
            float4 a0 = *(const float4*)&sxT[k][trow * 8];
            float4 a1 = *(const float4*)&sxT[k][trow * 8 + 4];
            float4 b0 = *(const float4*)&sw[k][tcol * 8];
            float4 b1 = *(const float4*)&sw[k][tcol * 8 + 4];
            float av[8] = {a0.x, a0.y, a0.z, a0.w, a1.x, a1.y, a1.z, a1.w};
            float bv[8] = {b0.x, b0.y, b0.z, b0.w, b1.x, b1.y, b1.z, b1.w};
            #pragma unroll
            for (int i = 0; i < 8; i++)
                #pragma unroll
                for (int j = 0; j < 8; j++)
                    acc[i][j] += av[i] * bv[j];
        }
        __syncthreads();
    }

    #pragma unroll
    for (int i = 0; i < 8; i++) {
        int gr = r0 + trow * 8 + i;
        if (gr >= N_NODES) continue;
        #pragma unroll
        for (int jj = 0; jj < 8; jj += 4) {
            int gc = tcol * 8 + jj;
            if (gc < H_DIM)
                *(float4*)&g_h1[gr * H_DIM + gc] =
                    make_float4(acc[i][jj], acc[i][jj+1], acc[i][jj+2], acc[i][jj+3]);
        }
    }
}

// ---------------------------------------------------------------- prop1 fused: gather + norm-on-the-fly + self-loop + bias + leaky
// Computes w = dinv[s] * dinv[gw] per edge (dinv broadcast loads) and stores
// g_val coalesced for prop2f's reuse.
__global__ void k_prop1f(const float* __restrict__ b1) {
    int gw   = (blockIdx.x * blockDim.x + threadIdx.x) >> 5;
    int lane = threadIdx.x & 31;
    if (gw >= N_NODES) return;
    int beg = g_rowptr[gw];
    int end = g_rowptr[gw + 1];
    bool act = lane < 25;
    int off = lane * 4;
    float di = g_dinv[gw];

    float4 acc = make_float4(0.f, 0.f, 0.f, 0.f);
    int j = beg;
    for (; j + 3 < end; j += 4) {
        int s0 = g_col[j], s1 = g_col[j+1], s2 = g_col[j+2], s3 = g_col[j+3];
        float w0 = g_dinv[s0] * di;
        float w1 = g_dinv[s1] * di;
        float w2 = g_dinv[s2] * di;
        float w3 = g_dinv[s3] * di;
        if (lane == 0) {
            g_val[j]   = w0;
            g_val[j+1] = w1;
            g_val[j+2] = w2;
            g_val[j+3] = w3;
        }
        if (act) {
            float4 v0 = *(const float4*)(g_h1 + s0 * H_DIM + off);
            float4 v1 = *(const float4*)(g_h1 + s1 * H_DIM + off);
            float4 v2 = *(const float4*)(g_h1 + s2 * H_DIM + off);
            float4 v3 = *(const float4*)(g_h1 + s3 * H_DIM + off);
            acc.x += w0*v0.x + w1*v1.x + w2*v2.x + w3*v3.x;
            acc.y += w0*v0.y + w1*v1.y + w2*v2.y + w3*v3.y;
            acc.z += w0*v0.z + w1*v1.z + w2*v2.z + w3*v3.z;
            acc.w += w0*v0.w + w1*v1.w + w2*v2.w + w3*v3.w;
        }
    }
    for (; j < end; j++) {
        int s = g_col[j];
        float w = g_dinv[s] * di;
        if (lane == 0) g_val[j] = w;
        if (act) {
            float4 v = *(const float4*)(g_h1 + s * H_DIM + off);
            acc.x += w*v.x; acc.y += w*v.y; acc.z += w*v.z; acc.w += w*v.w;
        }
    }
    if (act) {
        float sl = di * di;
        float4 own = *(const float4*)(g_h1 + gw * H_DIM + off);
        float4 bb  = *(const float4*)(b1 + off);
        float4 r;
        r.x = acc.x + sl * own.x + bb.x;
        r.y = acc.y + sl * own.y + bb.y;
        r.z = acc.z + sl * own.z + bb.z;
        r.w = acc.w + sl * own.w + bb.w;
        r.x = (r.x > 0.f) ? r.x : LEAKY * r.x;
        r.y = (r.y > 0.f) ? r.y : LEAKY * r.y;
        r.z = (r.z > 0.f) ? r.z : LEAKY * r.z;
        r.w = (r.w > 0.f) ? r.w : LEAKY * r.w;
        *(float4*)(g_h1p + gw * H_DIM + off) = r;
    }
}

// ---------------------------------------------------------------- GEMM2: g_h2 = h1p @ W2  (N x 100 @ 100 x 16)
__global__ void k_gemm2(const float* __restrict__ W2) {
    __shared__ __align__(16) float sh[64][101];
    __shared__ __align__(16) float sw[H_DIM * C_DIM];

    int tid = threadIdx.x;
    int r0  = blockIdx.x * 64;

    for (int i = tid; i < H_DIM * C_DIM; i += 128) sw[i] = W2[i];
    for (int i = tid; i < 64 * H_DIM; i += 128) {
        int r = i / H_DIM, c = i - r * H_DIM;
        int gr = r0 + r;
        sh[r][c] = (gr < N_NODES) ? g_h1p[gr * H_DIM + c] : 0.f;
    }
    __syncthreads();

    int cg = tid & 3;
    int rg = tid >> 2;
    float a0x=0,a0y=0,a0z=0,a0w=0, a1x=0,a1y=0,a1z=0,a1w=0;

    #pragma unroll 4
    for (int k = 0; k < H_DIM; k++) {
        float x0 = sh[rg * 2 + 0][k];
        float x1 = sh[rg * 2 + 1][k];
        float4 w = *(const float4*)&sw[k * C_DIM + cg * 4];
        a0x += x0 * w.x;  a0y += x0 * w.y;  a0z += x0 * w.z;  a0w += x0 * w.w;
        a1x += x1 * w.x;  a1y += x1 * w.y;  a1z += x1 * w.z;  a1w += x1 * w.w;
    }

    int gr0 = r0 + rg * 2;
    if (gr0 < N_NODES)
        *(float4*)&g_h2[gr0 * C_DIM + cg * 4] = make_float4(a0x, a0y, a0z, a0w);
    if (gr0 + 1 < N_NODES)
        *(float4*)&g_h2[(gr0 + 1) * C_DIM + cg * 4] = make_float4(a1x, a1y, a1z, a1w);
}

// ---------------------------------------------------------------- prop2 fused: gather + self-loop + bias + log_softmax
__global__ void k_prop2f(const float* __restrict__ b2, float* __restrict__ out) {
    int gw   = (blockIdx.x * blockDim.x + threadIdx.x) >> 5;
    int lane = threadIdx.x & 31;
    if (gw >= N_NODES) return;
    int beg = g_rowptr[gw];
    int end = g_rowptr[gw + 1];
    int sub = lane >> 4;
    int f   = lane & 15;

    float acc = 0.f;
    for (int j = beg + sub; j < end; j += 2) {
        int s = g_col[j];
        float w = g_val[j];
        acc += w * g_h2[s * C_DIM + f];
    }
    acc += __shfl_xor_sync(0xFFFFFFFFu, acc, 16);

    float di = g_dinv[gw];
    float v = acc + di * di * g_h2[gw * C_DIM + f] + b2[f];

    float m = v;
    #pragma unroll
    for (int s = 8; s >= 1; s >>= 1) m = fmaxf(m, __shfl_xor_sync(0xFFFFFFFFu, m, s));
    float ex = expf(v - m);
    float ssum = ex;
    #pragma unroll
    for (int s = 8; s >= 1; s >>= 1) ssum += __shfl_xor_sync(0xFFFFFFFFu, ssum, s);
    if (lane < 16) out[gw * C_DIM + f] = v - m - logf(ssum);
}

// ---------------------------------------------------------------- launch
extern "C" void kernel_launch(void* const* d_in, const int* in_sizes, int n_in,
                              void* d_out, int out_size) {
    const float* x  = (const float*)d_in[0];
    const float* W1 = (const float*)d_in[1];
    const float* b1 = (const float*)d_in[2];
    const float* W2 = (const float*)d_in[3];
    const float* b2 = (const float*)d_in[4];
    const int*   ei = (const int*)d_in[5];
    const int* src = ei;
    const int* dst = ei + N_EDGES;
    float* out = (float*)d_out;

    // Fork GEMM1 onto a side stream; CSR build runs concurrently on the main stream.
    cudaStream_t s2;
    cudaStreamCreate(&s2);
    cudaEvent_t ev_fork, ev_join;
    cudaEventCreateWithFlags(&ev_fork, cudaEventDisableTiming);
    cudaEventCreateWithFlags(&ev_join, cudaEventDisableTiming);

    cudaEventRecord(ev_fork, 0);
    cudaStreamWaitEvent(s2, ev_fork, 0);
    k_gemm1<<< (N_NODES + 127) / 128, 256, 0, s2 >>> (x, W1);
    cudaEventRecord(ev_join, s2);

    k_count <<< (N_EDGES / 8 + 255) / 256, 256 >>> (dst);
    k_scanF <<< SCAN_BLK, 1024 >>> ();
    k_build <<< (N_EDGES / 8 + 255) / 256, 256 >>> (src, dst);

    cudaStreamWaitEvent(0, ev_join, 0);
    k_prop1f<<< (N_NODES * 32 + 255) / 256, 256 >>> (b1);
    k_gemm2 <<< (N_NODES + 63) / 64, 128 >>> (W2);
    k_prop2f<<< (N_NODES * 32 + 255) / 256, 256 >>> (b2, out);
}

// round 10
// speedup vs baseline: 1.0665x; 1.0665x over previous
#include <cuda_runtime.h>

#define N_NODES 50000
#define N_EDGES 800000
#define F_IN    128
#define H_DIM   100
#define C_DIM   16
#define LEAKY   0.01f

#define SCAN_BLK 49              // ceil(50000/1024)

// ---- scratch (device globals; no allocation allowed) ----
__device__ __align__(16) float g_h1 [N_NODES * H_DIM];   // X @ W1
__device__ __align__(16) float g_h1p[N_NODES * H_DIM];   // leaky(conv1 out)
__device__ __align__(16) float g_h2 [N_NODES * C_DIM];   // h1p @ W2
__device__ float g_dinv[N_NODES];
__device__ __align__(16) int g_cnt[N_NODES];             // ZERO at entry (static init + scanF re-zero)
__device__ __align__(16) int g_rank[N_EDGES];            // edge rank within dst bucket
__device__ int   g_rowptr[N_NODES + 1];
__device__ __align__(16) int2 g_csr[N_EDGES];            // {src, bits(dinv[src])}
__device__ int   g_bsum[SCAN_BLK];
__device__ int            g_bar_cnt = 0;
__device__ volatile int   g_bar_gen = 0;

// ---------------------------------------------------------------- count + rank, 4 edges/thread
__global__ void k_count(const int* __restrict__ dst) {
    int t = blockIdx.x * blockDim.x + threadIdx.x;
    if (t < N_EDGES / 4) {
        int4 d = ((const int4*)dst)[t];
        int4 r;
        r.x = atomicAdd(&g_cnt[d.x], 1);
        r.y = atomicAdd(&g_cnt[d.y], 1);
        r.z = atomicAdd(&g_cnt[d.z], 1);
        r.w = atomicAdd(&g_cnt[d.w], 1);
        ((int4*)g_rank)[t] = r;
    }
}

// ---------------------------------------------------------------- fused scan (49 blocks, internal grid barrier)
// Also re-zeroes g_cnt to restore the entry invariant for the next replay.
__global__ void k_scanF() {
    __shared__ int wsum[32];
    __shared__ int s_pref[64];
    __shared__ int s_w0tot;
    int b = blockIdx.x, tid = threadIdx.x, lane = tid & 31, wid = tid >> 5;
    int i = b * 1024 + tid;
    int v = 0;
    if (i < N_NODES) {
        v = g_cnt[i];
        g_cnt[i] = 0;                       // restore invariant
    }

    int incl = v;
    #pragma unroll
    for (int off = 1; off < 32; off <<= 1) {
        int t = __shfl_up_sync(0xFFFFFFFFu, incl, off);
        if (lane >= off) incl += t;
    }
    if (lane == 31) wsum[wid] = incl;
    __syncthreads();
    if (wid == 0) {
        int wv = wsum[lane];
        int winc = wv;
        #pragma unroll
        for (int off = 1; off < 32; off <<= 1) {
            int t = __shfl_up_sync(0xFFFFFFFFu, winc, off);
            if (lane >= off) winc += t;
        }
        wsum[lane] = winc - wv;
        if (lane == 31) g_bsum[b] = winc;   // block total
    }
    __syncthreads();
    int excl_in_blk = wsum[wid] + incl - v;

    // 49-block grid barrier (co-resident: 49 < 148 SMs)
    __syncthreads();
    if (tid == 0) {
        __threadfence();
        int gen = g_bar_gen;
        if (atomicAdd(&g_bar_cnt, 1) == SCAN_BLK - 1) {
            g_bar_cnt = 0;
            __threadfence();
            g_bar_gen = gen + 1;
        } else {
            while (g_bar_gen == gen) __nanosleep(32);
            __threadfence();
        }
    }
    __syncthreads();

    // parallel exclusive scan of the 49 block totals (2 warps).
    if (tid < 64) {
        int bv = (tid < SCAN_BLK) ? g_bsum[tid] : 0;
        int binc = bv;
        #pragma unroll
        for (int off = 1; off < 32; off <<= 1) {
            int t = __shfl_up_sync(0xFFFFFFFFu, binc, off);
            if (lane >= off) binc += t;
        }
        s_pref[tid] = binc - bv;             // exclusive within warp
        if (tid == 31) s_w0tot = binc;       // warp-0 inclusive total (own slot; R6 race fix)
    }
    __syncthreads();
    if (tid >= 32 && tid < 64) s_pref[tid] += s_w0tot;
    __syncthreads();

    int e = s_pref[b] + excl_in_blk;
    if (i < N_NODES) {
        g_rowptr[i] = e;
        g_dinv[i]   = rsqrtf((float)(v + 1));
    }
    if (b == 0 && tid == 0) g_rowptr[N_NODES] = N_EDGES;
}

// ---------------------------------------------------------------- build CSR: single int2 {src, dinv[src]} store, 4 edges/thread
__global__ void k_build(const int* __restrict__ src, const int* __restrict__ dst) {
    int t = blockIdx.x * blockDim.x + threadIdx.x;
    if (t >= N_EDGES / 4) return;
    int4 s4 = ((const int4*)src)[t];
    int4 d4 = ((const int4*)dst)[t];
    int4 r4 = ((const int4*)g_rank)[t];
    int sv[4] = {s4.x, s4.y, s4.z, s4.w};
    int dv[4] = {d4.x, d4.y, d4.z, d4.w};
    int rv[4] = {r4.x, r4.y, r4.z, r4.w};
    #pragma unroll
    for (int k = 0; k < 4; k++) {
        int p = g_rowptr[dv[k]] + rv[k];
        g_csr[p] = make_int2(sv[k], __float_as_int(g_dinv[sv[k]]));
    }
}

// ---------------------------------------------------------------- GEMM1: g_h1 = x @ W1   (N x 128 @ 128 x 100)
__global__ void k_gemm1(const float* __restrict__ x, const float* __restrict__ W1) {
    __shared__ __align__(16) float sxT[8][128];
    __shared__ __align__(16) float sw [8][128];

    int tid  = threadIdx.x;
    int tcol = tid & 15;
    int trow = tid >> 4;
    int r0   = blockIdx.x * 128;

    float acc[8][8];
    #pragma unroll
    for (int i = 0; i < 8; i++)
        #pragma unroll
        for (int j = 0; j < 8; j++) acc[i][j] = 0.f;

    int xrow  = tid >> 1;
    int xhalf = tid & 1;
    int wrow  = tid >> 5;
    int wcol  = (tid & 31) * 4;

    for (int k0 = 0; k0 < F_IN; k0 += 8) {
        float4 xv = make_float4(0.f, 0.f, 0.f, 0.f);
        int gr = r0 + xrow;
        if (gr < N_NODES) xv = *(const float4*)&x[gr * F_IN + k0 + xhalf * 4];
        sxT[xhalf * 4 + 0][xrow] = xv.x;
        sxT[xhalf * 4 + 1][xrow] = xv.y;
        sxT[xhalf * 4 + 2][xrow] = xv.z;
        sxT[xhalf * 4 + 3][xrow] = xv.w;
        float4 wv = make_float4(0.f, 0.f, 0.f, 0.f);
        if (wcol < H_DIM) wv = *(const float4*)&W1[(k0 + wrow) * H_DIM + wcol];
        *(float4*)&sw[wrow][wcol] = wv;
        __syncthreads();

        #pragma unroll
        for (int k = 0; k < 8; k++) {
            float4 a0 = *(const float4*)&sxT[k][trow * 8];
            float4 a1 = *(const float4*)&sxT[k][trow * 8 + 4];
            float4 b0 = *(const float4*)&sw[k][tcol * 8];
            float4 b1 = *(const float4*)&sw[k][tcol * 8 + 4];
            float av[8] = {a0.x, a0.y, a0.z, a0.w, a1.x, a1.y, a1.z, a1.w};
            float bv[8] = {b0.x, b0.y, b0.z, b0.w, b1.x, b1.y, b1.z, b1.w};
            #pragma unroll
            for (int i = 0; i < 8; i++)
                #pragma unroll
                for (int j = 0; j < 8; j++)
                    acc[i][j] += av[i] * bv[j];
        }
        __syncthreads();
    }

    #pragma unroll
    for (int i = 0; i < 8; i++) {
        int gr = r0 + trow * 8 + i;
        if (gr >= N_NODES) continue;
        #pragma unroll
        for (int jj = 0; jj < 8; jj += 4) {
            int gc = tcol * 8 + jj;
            if (gc < H_DIM)
                *(float4*)&g_h1[gr * H_DIM + gc] =
                    make_float4(acc[i][jj], acc[i][jj+1], acc[i][jj+2], acc[i][jj+3]);
        }
    }
}

// ---------------------------------------------------------------- prop1 fused: gather + self-loop + bias + leaky
// w = csr.y * dinv[gw]; dinv[gw] is a register, csr is one broadcast sector.
__global__ void k_prop1f(const float* __restrict__ b1) {
    int gw   = (blockIdx.x * blockDim.x + threadIdx.x) >> 5;
    int lane = threadIdx.x & 31;
    if (gw >= N_NODES) return;
    int beg = g_rowptr[gw];
    int end = g_rowptr[gw + 1];
    bool act = lane < 25;
    int off = lane * 4;
    float di = g_dinv[gw];

    float4 acc = make_float4(0.f, 0.f, 0.f, 0.f);
    int j = beg;
    for (; j + 3 < end; j += 4) {
        int2 c0 = g_csr[j],   c1 = g_csr[j+1], c2 = g_csr[j+2], c3 = g_csr[j+3];
        float w0 = __int_as_float(c0.y) * di;
        float w1 = __int_as_float(c1.y) * di;
        float w2 = __int_as_float(c2.y) * di;
        float w3 = __int_as_float(c3.y) * di;
        if (act) {
            float4 v0 = *(const float4*)(g_h1 + c0.x * H_DIM + off);
            float4 v1 = *(const float4*)(g_h1 + c1.x * H_DIM + off);
            float4 v2 = *(const float4*)(g_h1 + c2.x * H_DIM + off);
            float4 v3 = *(const float4*)(g_h1 + c3.x * H_DIM + off);
            acc.x += w0*v0.x + w1*v1.x + w2*v2.x + w3*v3.x;
            acc.y += w0*v0.y + w1*v1.y + w2*v2.y + w3*v3.y;
            acc.z += w0*v0.z + w1*v1.z + w2*v2.z + w3*v3.z;
            acc.w += w0*v0.w + w1*v1.w + w2*v2.w + w3*v3.w;
        }
    }
    for (; j < end; j++) {
        int2 c = g_csr[j];
        float w = __int_as_float(c.y) * di;
        if (act) {
            float4 v = *(const float4*)(g_h1 + c.x * H_DIM + off);
            acc.x += w*v.x; acc.y += w*v.y; acc.z += w*v.z; acc.w += w*v.w;
        }
    }
    if (act) {
        float sl = di * di;
        float4 own = *(const float4*)(g_h1 + gw * H_DIM + off);
        float4 bb  = *(const float4*)(b1 + off);
        float4 r;
        r.x = acc.x + sl * own.x + bb.x;
        r.y = acc.y + sl * own.y + bb.y;
        r.z = acc.z + sl * own.z + bb.z;
        r.w = acc.w + sl * own.w + bb.w;
        r.x = (r.x > 0.f) ? r.x : LEAKY * r.x;
        r.y = (r.y > 0.f) ? r.y : LEAKY * r.y;
        r.z = (r.z > 0.f) ? r.z : LEAKY * r.z;
        r.w = (r.w > 0.f) ? r.w : LEAKY * r.w;
        *(float4*)(g_h1p + gw * H_DIM + off) = r;
    }
}

// ---------------------------------------------------------------- GEMM2: g_h2 = h1p @ W2  (N x 100 @ 100 x 16)
__global__ void k_gemm2(const float* __restrict__ W2) {
    __shared__ __align__(16) float sh[64][101];
    __shared__ __align__(16) float sw[H_DIM * C_DIM];

    int tid = threadIdx.x;
    int r0  = blockIdx.x * 64;

    for (int i = tid; i < H_DIM * C_DIM; i += 128) sw[i] = W2[i];
    for (int i = tid; i < 64 * H_DIM; i += 128) {
        int r = i / H_DIM, c = i - r * H_DIM;
        int gr = r0 + r;
        sh[r][c] = (gr < N_NODES) ? g_h1p[gr * H_DIM + c] : 0.f;
    }
    __syncthreads();

    int cg = tid & 3;
    int rg = tid >> 2;
    float a0x=0,a0y=0,a0z=0,a0w=0, a1x=0,a1y=0,a1z=0,a1w=0;

    #pragma unroll 4
    for (int k = 0; k < H_DIM; k++) {
        float x0 = sh[rg * 2 + 0][k];
        float x1 = sh[rg * 2 + 1][k];
        float4 w = *(const float4*)&sw[k * C_DIM + cg * 4];
        a0x += x0 * w.x;  a0y += x0 * w.y;  a0z += x0 * w.z;  a0w += x0 * w.w;
        a1x += x1 * w.x;  a1y += x1 * w.y;  a1z += x1 * w.z;  a1w += x1 * w.w;
    }

    int gr0 = r0 + rg * 2;
    if (gr0 < N_NODES)
        *(float4*)&g_h2[gr0 * C_DIM + cg * 4] = make_float4(a0x, a0y, a0z, a0w);
    if (gr0 + 1 < N_NODES)
        *(float4*)&g_h2[(gr0 + 1) * C_DIM + cg * 4] = make_float4(a1x, a1y, a1z, a1w);
}

// ---------------------------------------------------------------- prop2 fused: gather + self-loop + bias + log_softmax
__global__ void k_prop2f(const float* __restrict__ b2, float* __restrict__ out) {
    int gw   = (blockIdx.x * blockDim.x + threadIdx.x) >> 5;
    int lane = threadIdx.x & 31;
    if (gw >= N_NODES) return;
    int beg = g_rowptr[gw];
    int end = g_rowptr[gw + 1];
    int sub = lane >> 4;
    int f   = lane & 15;
    float di = g_dinv[gw];

    float acc = 0.f;
    for (int j = beg + sub; j < end; j += 2) {
        int2 c = g_csr[j];
        float w = __int_as_float(c.y) * di;
        acc += w * g_h2[c.x * C_DIM + f];
    }
    acc += __shfl_xor_sync(0xFFFFFFFFu, acc, 16);

    float v = acc + di * di * g_h2[gw * C_DIM + f] + b2[f];

    float m = v;
    #pragma unroll
    for (int s = 8; s >= 1; s >>= 1) m = fmaxf(m, __shfl_xor_sync(0xFFFFFFFFu, m, s));
    float ex = expf(v - m);
    float ssum = ex;
    #pragma unroll
    for (int s = 8; s >= 1; s >>= 1) ssum += __shfl_xor_sync(0xFFFFFFFFu, ssum, s);
    if (lane < 16) out[gw * C_DIM + f] = v - m - logf(ssum);
}

// ---------------------------------------------------------------- launch
extern "C" void kernel_launch(void* const* d_in, const int* in_sizes, int n_in,
                              void* d_out, int out_size) {
    const float* x  = (const float*)d_in[0];
    const float* W1 = (const float*)d_in[1];
    const float* b1 = (const float*)d_in[2];
    const float* W2 = (const float*)d_in[3];
    const float* b2 = (const float*)d_in[4];
    const int*   ei = (const int*)d_in[5];
    const int* src = ei;
    const int* dst = ei + N_EDGES;
    float* out = (float*)d_out;

    // Fork GEMM1 onto a side stream; CSR build runs concurrently on the main stream.
    cudaStream_t s2;
    cudaStreamCreate(&s2);
    cudaEvent_t ev_fork, ev_join;
    cudaEventCreateWithFlags(&ev_fork, cudaEventDisableTiming);
    cudaEventCreateWithFlags(&ev_join, cudaEventDisableTiming);

    cudaEventRecord(ev_fork, 0);
    cudaStreamWaitEvent(s2, ev_fork, 0);
    k_gemm1<<< (N_NODES + 127) / 128, 256, 0, s2 >>> (x, W1);
    cudaEventRecord(ev_join, s2);

    k_count <<< (N_EDGES / 4 + 255) / 256, 256 >>> (dst);
    k_scanF <<< SCAN_BLK, 1024 >>> ();
    k_build <<< (N_EDGES / 4 + 255) / 256, 256 >>> (src, dst);

    cudaStreamWaitEvent(0, ev_join, 0);
    k_prop1f<<< (N_NODES * 32 + 255) / 256, 256 >>> (b1);
    k_gemm2 <<< (N_NODES + 63) / 64, 128 >>> (W2);
    k_prop2f<<< (N_NODES * 32 + 255) / 256, 256 >>> (b2, out);
}

// round 12
// speedup vs baseline: 1.1322x; 1.0616x over previous
#include <cuda_runtime.h>
#include <cuda_fp16.h>

#define N_NODES 50000
#define N_EDGES 800000
#define F_IN    128
#define H_DIM   100
#define C_DIM   16
#define LEAKY   0.01f

#define SCAN_BLK 49              // ceil(50000/1024)

// ---- scratch (device globals; no allocation allowed) ----
__device__ __align__(16) __half g_h1 [N_NODES * H_DIM];  // X @ W1 (fp16 storage)
__device__ __align__(16) float  g_h1p[N_NODES * H_DIM];  // leaky(conv1 out), fp32
__device__ __align__(16) __half g_h2 [N_NODES * C_DIM];  // h1p @ W2 (fp16 storage)
__device__ float g_dinv[N_NODES];
__device__ __align__(16) int g_cnt[N_NODES];             // ZERO at entry (static init + scanF re-zero)
__device__ __align__(16) int g_rank[N_EDGES];            // edge rank within dst bucket
__device__ int   g_rowptr[N_NODES + 1];
__device__ __align__(16) int2 g_csr[N_EDGES];            // {src, bits(dinv[src])}
__device__ int   g_bsum[SCAN_BLK];
__device__ int            g_bar_cnt = 0;
__device__ volatile int   g_bar_gen = 0;

// ---------------------------------------------------------------- count + rank, 4 edges/thread
__global__ void k_count(const int* __restrict__ dst) {
    int t = blockIdx.x * blockDim.x + threadIdx.x;
    if (t < N_EDGES / 4) {
        int4 d = ((const int4*)dst)[t];
        int4 r;
        r.x = atomicAdd(&g_cnt[d.x], 1);
        r.y = atomicAdd(&g_cnt[d.y], 1);
        r.z = atomicAdd(&g_cnt[d.z], 1);
        r.w = atomicAdd(&g_cnt[d.w], 1);
        ((int4*)g_rank)[t] = r;
    }
}

// ---------------------------------------------------------------- fused scan (49 blocks, internal grid barrier)
__global__ void k_scanF() {
    __shared__ int wsum[32];
    __shared__ int s_pref[64];
    __shared__ int s_w0tot;
    int b = blockIdx.x, tid = threadIdx.x, lane = tid & 31, wid = tid >> 5;
    int i = b * 1024 + tid;
    int v = 0;
    if (i < N_NODES) {
        v = g_cnt[i];
        g_cnt[i] = 0;                       // restore invariant
    }

    int incl = v;
    #pragma unroll
    for (int off = 1; off < 32; off <<= 1) {
        int t = __shfl_up_sync(0xFFFFFFFFu, incl, off);
        if (lane >= off) incl += t;
    }
    if (lane == 31) wsum[wid] = incl;
    __syncthreads();
    if (wid == 0) {
        int wv = wsum[lane];
        int winc = wv;
        #pragma unroll
        for (int off = 1; off < 32; off <<= 1) {
            int t = __shfl_up_sync(0xFFFFFFFFu, winc, off);
            if (lane >= off) winc += t;
        }
        wsum[lane] = winc - wv;
        if (lane == 31) g_bsum[b] = winc;   // block total
    }
    __syncthreads();
    int excl_in_blk = wsum[wid] + incl - v;

    // 49-block grid barrier (co-resident: 49 < 148 SMs)
    __syncthreads();
    if (tid == 0) {
        __threadfence();
        int gen = g_bar_gen;
        if (atomicAdd(&g_bar_cnt, 1) == SCAN_BLK - 1) {
            g_bar_cnt = 0;
            __threadfence();
            g_bar_gen = gen + 1;
        } else {
            while (g_bar_gen == gen) __nanosleep(32);
            __threadfence();
        }
    }
    __syncthreads();

    // parallel exclusive scan of the 49 block totals (2 warps).
    if (tid < 64) {
        int bv = (tid < SCAN_BLK) ? g_bsum[tid] : 0;
        int binc = bv;
        #pragma unroll
        for (int off = 1; off < 32; off <<= 1) {
            int t = __shfl_up_sync(0xFFFFFFFFu, binc, off);
            if (lane >= off) binc += t;
        }
        s_pref[tid] = binc - bv;             // exclusive within warp
        if (tid == 31) s_w0tot = binc;       // warp-0 inclusive total (own slot; R6 race fix)
    }
    __syncthreads();
    if (tid >= 32 && tid < 64) s_pref[tid] += s_w0tot;
    __syncthreads();

    int e = s_pref[b] + excl_in_blk;
    if (i < N_NODES) {
        g_rowptr[i] = e;
        g_dinv[i]   = rsqrtf((float)(v + 1));
    }
    if (b == 0 && tid == 0) g_rowptr[N_NODES] = N_EDGES;
}

// ---------------------------------------------------------------- build CSR: single int2 {src, dinv[src]} store, 4 edges/thread
__global__ void k_build(const int* __restrict__ src, const int* __restrict__ dst) {
    int t = blockIdx.x * blockDim.x + threadIdx.x;
    if (t >= N_EDGES / 4) return;
    int4 s4 = ((const int4*)src)[t];
    int4 d4 = ((const int4*)dst)[t];
    int4 r4 = ((const int4*)g_rank)[t];
    int sv[4] = {s4.x, s4.y, s4.z, s4.w};
    int dv[4] = {d4.x, d4.y, d4.z, d4.w};
    int rv[4] = {r4.x, r4.y, r4.z, r4.w};
    #pragma unroll
    for (int k = 0; k < 4; k++) {
        int p = g_rowptr[dv[k]] + rv[k];
        g_csr[p] = make_int2(sv[k], __float_as_int(g_dinv[sv[k]]));
    }
}

// ---------------------------------------------------------------- GEMM1: g_h1 = fp16(x @ W1)   (N x 128 @ 128 x 100)
__global__ void k_gemm1(const float* __restrict__ x, const float* __restrict__ W1) {
    __shared__ __align__(16) float sxT[8][128];
    __shared__ __align__(16) float sw [8][128];

    int tid  = threadIdx.x;
    int tcol = tid & 15;
    int trow = tid >> 4;
    int r0   = blockIdx.x * 128;

    float acc[8][8];
    #pragma unroll
    for (int i = 0; i < 8; i++)
        #pragma unroll
        for (int j = 0; j < 8; j++) acc[i][j] = 0.f;

    int xrow  = tid >> 1;
    int xhalf = tid & 1;
    int wrow  = tid >> 5;
    int wcol  = (tid & 31) * 4;

    for (int k0 = 0; k0 < F_IN; k0 += 8) {
        float4 xv = make_float4(0.f, 0.f, 0.f, 0.f);
        int gr = r0 + xrow;
        if (gr < N_NODES) xv = *(const float4*)&x[gr * F_IN + k0 + xhalf * 4];
        sxT[xhalf * 4 + 0][xrow] = xv.x;
        sxT[xhalf * 4 + 1][xrow] = xv.y;
        sxT[xhalf * 4 + 2][xrow] = xv.z;
        sxT[xhalf * 4 + 3][xrow] = xv.w;
        float4 wv = make_float4(0.f, 0.f, 0.f, 0.f);
        if (wcol < H_DIM) wv = *(const float4*)&W1[(k0 + wrow) * H_DIM + wcol];
        *(float4*)&sw[wrow][wcol] = wv;
        __syncthreads();

        #pragma unroll
        for (int k = 0; k < 8; k++) {
            float4 a0 = *(const float4*)&sxT[k][trow * 8];
            float4 a1 = *(const float4*)&sxT[k][trow * 8 + 4];
            float4 b0 = *(const float4*)&sw[k][tcol * 8];
            float4 b1 = *(const float4*)&sw[k][tcol * 8 + 4];
            float av[8] = {a0.x, a0.y, a0.z, a0.w, a1.x, a1.y, a1.z, a1.w};
            float bv[8] = {b0.x, b0.y, b0.z, b0.w, b1.x, b1.y, b1.z, b1.w};
            #pragma unroll
            for (int i = 0; i < 8; i++)
                #pragma unroll
                for (int j = 0; j < 8; j++)
                    acc[i][j] += av[i] * bv[j];
        }
        __syncthreads();
    }

    #pragma unroll
    for (int i = 0; i < 8; i++) {
        int gr = r0 + trow * 8 + i;
        if (gr >= N_NODES) continue;
        #pragma unroll
        for (int jj = 0; jj < 8; jj += 4) {
            int gc = tcol * 8 + jj;
            if (gc < H_DIM) {   // gc multiple of 4 -> 8B-aligned half store
                __half2 p0 = __floats2half2_rn(acc[i][jj],   acc[i][jj+1]);
                __half2 p1 = __floats2half2_rn(acc[i][jj+2], acc[i][jj+3]);
                __half2* dstp = (__half2*)&g_h1[gr * H_DIM + gc];
                dstp[0] = p0;
                dstp[1] = p1;
            }
        }
    }
}

// ---------------------------------------------------------------- prop1 fused: fp16 gather + self-loop + bias + leaky
__global__ void k_prop1f(const float* __restrict__ b1) {
    int gw   = (blockIdx.x * blockDim.x + threadIdx.x) >> 5;
    int lane = threadIdx.x & 31;
    if (gw >= N_NODES) return;
    int beg = g_rowptr[gw];
    int end = g_rowptr[gw + 1];
    bool act = lane < 25;
    int off = lane * 4;                    // half index; byte offset lane*8 (8B aligned)
    float di = g_dinv[gw];

    float4 acc = make_float4(0.f, 0.f, 0.f, 0.f);
    int j = beg;
    for (; j + 3 < end; j += 4) {
        int2 c0 = g_csr[j],   c1 = g_csr[j+1], c2 = g_csr[j+2], c3 = g_csr[j+3];
        float w0 = __int_as_float(c0.y) * di;
        float w1 = __int_as_float(c1.y) * di;
        float w2 = __int_as_float(c2.y) * di;
        float w3 = __int_as_float(c3.y) * di;
        if (act) {
            __half2 a0 = *(const __half2*)(g_h1 + c0.x * H_DIM + off);
            __half2 b0 = *(const __half2*)(g_h1 + c0.x * H_DIM + off + 2);
            __half2 a1 = *(const __half2*)(g_h1 + c1.x * H_DIM + off);
            __half2 b1h= *(const __half2*)(g_h1 + c1.x * H_DIM + off + 2);
            __half2 a2 = *(const __half2*)(g_h1 + c2.x * H_DIM + off);
            __half2 b2h= *(const __half2*)(g_h1 + c2.x * H_DIM + off + 2);
            __half2 a3 = *(const __half2*)(g_h1 + c3.x * H_DIM + off);
            __half2 b3h= *(const __half2*)(g_h1 + c3.x * H_DIM + off + 2);
            float2 f0a = __half22float2(a0), f0b = __half22float2(b0);
            float2 f1a = __half22float2(a1), f1b = __half22float2(b1h);
            float2 f2a = __half22float2(a2), f2b = __half22float2(b2h);
            float2 f3a = __half22float2(a3), f3b = __half22float2(b3h);
            acc.x += w0*f0a.x + w1*f1a.x + w2*f2a.x + w3*f3a.x;
            acc.y += w0*f0a.y + w1*f1a.y + w2*f2a.y + w3*f3a.y;
            acc.z += w0*f0b.x + w1*f1b.x + w2*f2b.x + w3*f3b.x;
            acc.w += w0*f0b.y + w1*f1b.y + w2*f2b.y + w3*f3b.y;
        }
    }
    for (; j < end; j++) {
        int2 c = g_csr[j];
        float w = __int_as_float(c.y) * di;
        if (act) {
            __half2 a = *(const __half2*)(g_h1 + c.x * H_DIM + off);
            __half2 b = *(const __half2*)(g_h1 + c.x * H_DIM + off + 2);
            float2 fa = __half22float2(a), fb = __half22float2(b);
            acc.x += w*fa.x; acc.y += w*fa.y; acc.z += w*fb.x; acc.w += w*fb.y;
        }
    }
    if (act) {
        float sl = di * di;
        __half2 oa = *(const __half2*)(g_h1 + gw * H_DIM + off);
        __half2 ob = *(const __half2*)(g_h1 + gw * H_DIM + off + 2);
        float2 foa = __half22float2(oa), fob = __half22float2(ob);
        float4 bb  = *(const float4*)(b1 + off);
        float4 r;
        r.x = acc.x + sl * foa.x + bb.x;
        r.y = acc.y + sl * foa.y + bb.y;
        r.z = acc.z + sl * fob.x + bb.z;
        r.w = acc.w + sl * fob.y + bb.w;
        r.x = (r.x > 0.f) ? r.x : LEAKY * r.x;
        r.y = (r.y > 0.f) ? r.y : LEAKY * r.y;
        r.z = (r.z > 0.f) ? r.z : LEAKY * r.z;
        r.w = (r.w > 0.f) ? r.w : LEAKY * r.w;
        *(float4*)(g_h1p + gw * H_DIM + off) = r;
    }
}

// ---------------------------------------------------------------- GEMM2: g_h2 = fp16(h1p @ W2)  (N x 100 @ 100 x 16)
__global__ void k_gemm2(const float* __restrict__ W2) {
    __shared__ __align__(16) float sh[64][101];
    __shared__ __align__(16) float sw[H_DIM * C_DIM];

    int tid = threadIdx.x;
    int r0  = blockIdx.x * 64;

    for (int i = tid; i < H_DIM * C_DIM; i += 128) sw[i] = W2[i];
    for (int i = tid; i < 64 * H_DIM; i += 128) {
        int r = i / H_DIM, c = i - r * H_DIM;
        int gr = r0 + r;
        sh[r][c] = (gr < N_NODES) ? g_h1p[gr * H_DIM + c] : 0.f;
    }
    __syncthreads();

    int cg = tid & 3;
    int rg = tid >> 2;
    float a0x=0,a0y=0,a0z=0,a0w=0, a1x=0,a1y=0,a1z=0,a1w=0;

    #pragma unroll 4
    for (int k = 0; k < H_DIM; k++) {
        float x0 = sh[rg * 2 + 0][k];
        float x1 = sh[rg * 2 + 1][k];
        float4 w = *(const float4*)&sw[k * C_DIM + cg * 4];
        a0x += x0 * w.x;  a0y += x0 * w.y;  a0z += x0 * w.z;  a0w += x0 * w.w;
        a1x += x1 * w.x;  a1y += x1 * w.y;  a1z += x1 * w.z;  a1w += x1 * w.w;
    }

    int gr0 = r0 + rg * 2;
    if (gr0 < N_NODES) {
        __half2* p = (__half2*)&g_h2[gr0 * C_DIM + cg * 4];
        p[0] = __floats2half2_rn(a0x, a0y);
        p[1] = __floats2half2_rn(a0z, a0w);
    }
    if (gr0 + 1 < N_NODES) {
        __half2* p = (__half2*)&g_h2[(gr0 + 1) * C_DIM + cg * 4];
        p[0] = __floats2half2_rn(a1x, a1y);
        p[1] = __floats2half2_rn(a1z, a1w);
    }
}

// ---------------------------------------------------------------- prop2 fused: fp16 gather + self-loop + bias + log_softmax
__global__ void k_prop2f(const float* __restrict__ b2, float* __restrict__ out) {
    int gw   = (blockIdx.x * blockDim.x + threadIdx.x) >> 5;
    int lane = threadIdx.x & 31;
    if (gw >= N_NODES) return;
    int beg = g_rowptr[gw];
    int end = g_rowptr[gw + 1];
    int sub = lane >> 4;
    int f   = lane & 15;
    float di = g_dinv[gw];

    float acc = 0.f;
    for (int j = beg + sub; j < end; j += 2) {
        int2 c = g_csr[j];
        float w = __int_as_float(c.y) * di;
        acc += w * __half2float(g_h2[c.x * C_DIM + f]);
    }
    acc += __shfl_xor_sync(0xFFFFFFFFu, acc, 16);

    float v = acc + di * di * __half2float(g_h2[gw * C_DIM + f]) + b2[f];

    float m = v;
    #pragma unroll
    for (int s = 8; s >= 1; s >>= 1) m = fmaxf(m, __shfl_xor_sync(0xFFFFFFFFu, m, s));
    float ex = expf(v - m);
    float ssum = ex;
    #pragma unroll
    for (int s = 8; s >= 1; s >>= 1) ssum += __shfl_xor_sync(0xFFFFFFFFu, ssum, s);
    if (lane < 16) out[gw * C_DIM + f] = v - m - logf(ssum);
}

// ---------------------------------------------------------------- launch
extern "C" void kernel_launch(void* const* d_in, const int* in_sizes, int n_in,
                              void* d_out, int out_size) {
    const float* x  = (const float*)d_in[0];
    const float* W1 = (const float*)d_in[1];
    const float* b1 = (const float*)d_in[2];
    const float* W2 = (const float*)d_in[3];
    const float* b2 = (const float*)d_in[4];
    const int*   ei = (const int*)d_in[5];
    const int* src = ei;
    const int* dst = ei + N_EDGES;
    float* out = (float*)d_out;

    // Fork GEMM1 onto a side stream; CSR build runs concurrently on the main stream.
    cudaStream_t s2;
    cudaStreamCreate(&s2);
    cudaEvent_t ev_fork, ev_join;
    cudaEventCreateWithFlags(&ev_fork, cudaEventDisableTiming);
    cudaEventCreateWithFlags(&ev_join, cudaEventDisableTiming);

    cudaEventRecord(ev_fork, 0);
    cudaStreamWaitEvent(s2, ev_fork, 0);
    k_gemm1<<< (N_NODES + 127) / 128, 256, 0, s2 >>> (x, W1);
    cudaEventRecord(ev_join, s2);

    k_count <<< (N_EDGES / 4 + 255) / 256, 256 >>> (dst);
    k_scanF <<< SCAN_BLK, 1024 >>> ();
    k_build <<< (N_EDGES / 4 + 255) / 256, 256 >>> (src, dst);

    cudaStreamWaitEvent(0, ev_join, 0);
    k_prop1f<<< (N_NODES * 32 + 255) / 256, 256 >>> (b1);
    k_gemm2 <<< (N_NODES + 63) / 64, 128 >>> (W2);
    k_prop2f<<< (N_NODES * 32 + 255) / 256, 256 >>> (b2, out);
}